// round 1
// baseline (speedup 1.0000x reference)
#include <cuda_runtime.h>
#include <cuda_bf16.h>

// Problem constants (fixed shapes from reference):
//   batch_x: [32, 4096, 128] -> flat rows: N=4096 rows x 4096 (I=64 patches of L=64)
//   pred:    [32, 1024, 128] -> flat rows: N=4096 rows x 1024 (J=16 patches of L=64)
#define NROWS 4096
#define SEQ   4096
#define PREDL 1024
#define LPATCH 64
#define I_PATCH 64
#define J_PATCH 16
#define LP_STRIDE 68   // 64 + 4 pad: float4-aligned, decorrelates banks
#define Q_STRIDE  68

__device__ float g_row_sum[NROWS];

__global__ __launch_bounds__(256, 4)
void kl_row_kernel(const float* __restrict__ x, const float* __restrict__ pred) {
    __shared__ float lp[I_PATCH * LP_STRIDE];   // log_softmax(x patches)   [64][68]
    __shared__ float qs[J_PATCH * Q_STRIDE];    // softmax(pred patches)    [16][68]
    __shared__ float neg_ent[J_PATCH];          // sum_l q*log_q per j
    __shared__ float red[8];

    const int n    = blockIdx.x;
    const int tid  = threadIdx.x;
    const int warp = tid >> 5;
    const int lane = tid & 31;

    // ---------------- Phase A: log_softmax over x patches ----------------
    {
        const float* xrow = x + (size_t)n * SEQ;
        #pragma unroll
        for (int p = warp; p < I_PATCH; p += 8) {
            float2 v = ((const float2*)(xrow + p * LPATCH))[lane];
            float m = fmaxf(v.x, v.y);
            #pragma unroll
            for (int o = 16; o; o >>= 1) m = fmaxf(m, __shfl_xor_sync(0xffffffffu, m, o));
            float e = __expf(v.x - m) + __expf(v.y - m);
            #pragma unroll
            for (int o = 16; o; o >>= 1) e += __shfl_xor_sync(0xffffffffu, e, o);
            float lse = m + __logf(e);
            ((float2*)(lp + p * LP_STRIDE))[lane] = make_float2(v.x - lse, v.y - lse);
        }
    }

    // ---------- Phase B: log_softmax over pred patches, q, neg_ent ----------
    {
        const float* prow = pred + (size_t)n * PREDL;
        #pragma unroll
        for (int p = warp; p < J_PATCH; p += 8) {
            float2 v = ((const float2*)(prow + p * LPATCH))[lane];
            float m = fmaxf(v.x, v.y);
            #pragma unroll
            for (int o = 16; o; o >>= 1) m = fmaxf(m, __shfl_xor_sync(0xffffffffu, m, o));
            float e0 = __expf(v.x - m);
            float e1 = __expf(v.y - m);
            float e = e0 + e1;
            #pragma unroll
            for (int o = 16; o; o >>= 1) e += __shfl_xor_sync(0xffffffffu, e, o);
            float rinv = __frcp_rn(e);
            float lse  = m + __logf(e);
            float q0 = e0 * rinv, q1 = e1 * rinv;
            float lq0 = v.x - lse, lq1 = v.y - lse;
            ((float2*)(qs + p * Q_STRIDE))[lane] = make_float2(q0, q1);
            float ne = q0 * lq0 + q1 * lq1;
            #pragma unroll
            for (int o = 16; o; o >>= 1) ne += __shfl_xor_sync(0xffffffffu, ne, o);
            if (lane == 0) neg_ent[p] = ne;
        }
    }
    __syncthreads();

    // ---------------- Phase C: cross GEMM + KL + softmax over j ----------------
    // thread t: j = t & 15, ib = t >> 4; handles i in {ib, ib+16, ib+32, ib+48}
    const int j  = tid & 15;
    const int ib = tid >> 4;

    float acc0 = 0.f, acc1 = 0.f, acc2 = 0.f, acc3 = 0.f;
    const float4* q4 = (const float4*)(qs + j * Q_STRIDE);
    const float* lp0 = lp + (ib +  0) * LP_STRIDE;
    const float* lp1 = lp + (ib + 16) * LP_STRIDE;
    const float* lp2 = lp + (ib + 32) * LP_STRIDE;
    const float* lp3 = lp + (ib + 48) * LP_STRIDE;

    #pragma unroll
    for (int l4 = 0; l4 < LPATCH / 4; l4++) {
        float4 qv = q4[l4];
        float4 a = ((const float4*)lp0)[l4];
        float4 b = ((const float4*)lp1)[l4];
        float4 c = ((const float4*)lp2)[l4];
        float4 d = ((const float4*)lp3)[l4];
        acc0 += qv.x * a.x + qv.y * a.y + qv.z * a.z + qv.w * a.w;
        acc1 += qv.x * b.x + qv.y * b.y + qv.z * b.z + qv.w * b.w;
        acc2 += qv.x * c.x + qv.y * c.y + qv.z * c.z + qv.w * c.w;
        acc3 += qv.x * d.x + qv.y * d.y + qv.z * d.z + qv.w * d.w;
    }

    const float ne_j = neg_ent[j];
    float kl[4];
    kl[0] = ne_j - acc0;
    kl[1] = ne_j - acc1;
    kl[2] = ne_j - acc2;
    kl[3] = ne_j - acc3;

    // For each i: softmax over j (the 16 lanes sharing ib), contribution = sum_j w*kl
    float my_sum = 0.f;
    #pragma unroll
    for (int k = 0; k < 4; k++) {
        float v = kl[k];
        float m = v;
        #pragma unroll
        for (int o = 8; o; o >>= 1) m = fmaxf(m, __shfl_xor_sync(0xffffffffu, m, o));
        float e   = __expf(v - m);
        float ekl = e * v;
        #pragma unroll
        for (int o = 8; o; o >>= 1) {
            e   += __shfl_xor_sync(0xffffffffu, e, o);
            ekl += __shfl_xor_sync(0xffffffffu, ekl, o);
        }
        if (j == 0) my_sum += ekl / e;
    }

    // Block reduction (deterministic)
    #pragma unroll
    for (int o = 16; o; o >>= 1) my_sum += __shfl_xor_sync(0xffffffffu, my_sum, o);
    if (lane == 0) red[warp] = my_sum;
    __syncthreads();
    if (warp == 0) {
        float v = (lane < 8) ? red[lane] : 0.f;
        #pragma unroll
        for (int o = 4; o; o >>= 1) v += __shfl_xor_sync(0xffffffffu, v, o);
        if (lane == 0) g_row_sum[n] = v;
    }
}

__global__ __launch_bounds__(256)
void kl_reduce_kernel(float* __restrict__ out) {
    __shared__ float red[8];
    const int tid  = threadIdx.x;
    const int warp = tid >> 5;
    const int lane = tid & 31;
    float s = 0.f;
    #pragma unroll 4
    for (int i = tid; i < NROWS; i += 256) s += g_row_sum[i];
    #pragma unroll
    for (int o = 16; o; o >>= 1) s += __shfl_xor_sync(0xffffffffu, s, o);
    if (lane == 0) red[warp] = s;
    __syncthreads();
    if (warp == 0) {
        float v = (lane < 8) ? red[lane] : 0.f;
        #pragma unroll
        for (int o = 4; o; o >>= 1) v += __shfl_xor_sync(0xffffffffu, v, o);
        if (lane == 0) out[0] = v * (1.0f / (float)NROWS);
    }
}

extern "C" void kernel_launch(void* const* d_in, const int* in_sizes, int n_in,
                              void* d_out, int out_size) {
    const float* x = nullptr;
    const float* pred = nullptr;
    for (int i = 0; i < n_in; i++) {
        if (in_sizes[i] == 32 * 4096 * 128)      x    = (const float*)d_in[i];
        else if (in_sizes[i] == 32 * 1024 * 128) pred = (const float*)d_in[i];
    }
    kl_row_kernel<<<NROWS, 256>>>(x, pred);
    kl_reduce_kernel<<<1, 256>>>((float*)d_out);
}

// round 2
// speedup vs baseline: 1.2282x; 1.2282x over previous
#include <cuda_runtime.h>
#include <cuda_bf16.h>

// Shapes: batch_x [32,4096,128] -> N=4096 rows x 4096 (I=64 patches, L=64)
//         pred    [32,1024,128] -> N=4096 rows x 1024 (J=16 patches, L=64)
//
// Math (after simplification, using sum_l q_jl = 1):
//   dot_ij = q_j . x_i  (raw x!)
//   u_ij   = ne_j - dot_ij                   (ne_j = sum q log q)
//   w_ij   = softmax_j(u_ij)                 (lse_i cancels)
//   loss   = mean_n [ sum_i ( sum_j w_ij u_ij + lse_i ) ]
#define NROWS 4096
#define SEQ   4096
#define PREDL 1024
#define XS_STRIDE 68
#define QS_STRIDE 68

__device__ float g_row_sum[NROWS];
__device__ unsigned g_ctr;   // zero-initialized; last block resets to 0

__device__ __forceinline__ unsigned long long pk2(float a, float b) {
    unsigned long long r;
    asm("mov.b64 %0, {%1, %2};" : "=l"(r) : "f"(a), "f"(b));
    return r;
}
__device__ __forceinline__ void fma2(unsigned long long& d,
                                     unsigned long long a, unsigned long long b) {
    asm("fma.rn.f32x2 %0, %1, %2, %0;" : "+l"(d) : "l"(a), "l"(b));
}
__device__ __forceinline__ float2 unpk2(unsigned long long v) {
    float2 r;
    asm("mov.b64 {%0, %1}, %2;" : "=f"(r.x), "=f"(r.y) : "l"(v));
    return r;
}

__global__ __launch_bounds__(256, 4)
void kl_fused_kernel(const float* __restrict__ x, const float* __restrict__ pred,
                     float* __restrict__ out) {
    __shared__ float xs[64 * XS_STRIDE];   // raw x patches [64][68]
    __shared__ float qs[16 * QS_STRIDE];   // softmax(pred) [16][68]
    __shared__ float ne[16];
    __shared__ float red[8];
    __shared__ int   is_last_sh;

    const int n   = blockIdx.x;
    const int t   = threadIdx.x;
    const int g16 = t & 15;     // lane within 16-group
    const int p0  = t >> 4;     // 0..15

    // ---- Phase A: load raw x -> smem; compute lse_i per patch from registers ----
    float lse_part = 0.f;
    {
        const float4* x4 = (const float4*)(x + (size_t)n * SEQ);
        float4 xv[4];
        #pragma unroll
        for (int k = 0; k < 4; k++) xv[k] = x4[t + 256 * k];
        #pragma unroll
        for (int k = 0; k < 4; k++)
            ((float4*)(xs + (p0 + 16 * k) * XS_STRIDE))[g16] = xv[k];
        // thread's k-th float4 belongs to patch p0+16k, 16 threads per patch
        #pragma unroll
        for (int k = 0; k < 4; k++) {
            float4 v = xv[k];
            float m = fmaxf(fmaxf(v.x, v.y), fmaxf(v.z, v.w));
            #pragma unroll
            for (int o = 8; o; o >>= 1) m = fmaxf(m, __shfl_xor_sync(0xffffffffu, m, o));
            float E = __expf(v.x - m) + __expf(v.y - m) + __expf(v.z - m) + __expf(v.w - m);
            #pragma unroll
            for (int o = 8; o; o >>= 1) E += __shfl_xor_sync(0xffffffffu, E, o);
            if (g16 == 0) lse_part += m + __logf(E);
        }
    }

    // ---- Phase B: pred patches -> q (smem) and ne_j, from registers ----
    {
        const float4* pr4 = (const float4*)(pred + (size_t)n * PREDL);
        float4 v = pr4[t];                       // patch p0, offset g16*4
        float m = fmaxf(fmaxf(v.x, v.y), fmaxf(v.z, v.w));
        #pragma unroll
        for (int o = 8; o; o >>= 1) m = fmaxf(m, __shfl_xor_sync(0xffffffffu, m, o));
        float e0 = __expf(v.x - m), e1 = __expf(v.y - m);
        float e2 = __expf(v.z - m), e3 = __expf(v.w - m);
        float E = e0 + e1 + e2 + e3;
        float S = e0 * v.x + e1 * v.y + e2 * v.z + e3 * v.w;  // sum e*v
        #pragma unroll
        for (int o = 8; o; o >>= 1) {
            E += __shfl_xor_sync(0xffffffffu, E, o);
            S += __shfl_xor_sync(0xffffffffu, S, o);
        }
        float rinv = __frcp_rn(E);
        float lse  = m + __logf(E);
        ((float4*)(qs + p0 * QS_STRIDE))[g16] =
            make_float4(e0 * rinv, e1 * rinv, e2 * rinv, e3 * rinv);
        if (g16 == 0) ne[p0] = S * rinv - lse;   // sum q*(v-lse)
    }
    __syncthreads();

    // ---- Phase C: dot_ij = q_j . x_i via packed f32x2 FMA ----
    // thread t: j = g16, i in {p0, p0+16, p0+32, p0+48}
    const int j = g16;
    unsigned long long acc0 = 0ull, acc1 = 0ull, acc2 = 0ull, acc3 = 0ull; // (0.f,0.f)
    {
        const float4* q4 = (const float4*)(qs + j * QS_STRIDE);
        const float4* r0 = (const float4*)(xs + (p0 +  0) * XS_STRIDE);
        const float4* r1 = (const float4*)(xs + (p0 + 16) * XS_STRIDE);
        const float4* r2 = (const float4*)(xs + (p0 + 32) * XS_STRIDE);
        const float4* r3 = (const float4*)(xs + (p0 + 48) * XS_STRIDE);
        #pragma unroll
        for (int l = 0; l < 16; l++) {
            float4 qv = q4[l];
            unsigned long long qa = pk2(qv.x, qv.y);
            unsigned long long qb = pk2(qv.z, qv.w);
            float4 a = r0[l];
            fma2(acc0, qa, pk2(a.x, a.y)); fma2(acc0, qb, pk2(a.z, a.w));
            float4 b = r1[l];
            fma2(acc1, qa, pk2(b.x, b.y)); fma2(acc1, qb, pk2(b.z, b.w));
            float4 c = r2[l];
            fma2(acc2, qa, pk2(c.x, c.y)); fma2(acc2, qb, pk2(c.z, c.w));
            float4 d = r3[l];
            fma2(acc3, qa, pk2(d.x, d.y)); fma2(acc3, qb, pk2(d.z, d.w));
        }
    }
    float2 a0 = unpk2(acc0), a1 = unpk2(acc1), a2 = unpk2(acc2), a3 = unpk2(acc3);
    const float nej = ne[j];
    float u[4];
    u[0] = nej - (a0.x + a0.y);
    u[1] = nej - (a1.x + a1.y);
    u[2] = nej - (a2.x + a2.y);
    u[3] = nej - (a3.x + a3.y);

    // ---- softmax over j (16 lanes) per i; contribution = (sum e*u)/(sum e) ----
    float csum = 0.f;
    #pragma unroll
    for (int k = 0; k < 4; k++) {
        float v = u[k];
        float m = v;
        #pragma unroll
        for (int o = 8; o; o >>= 1) m = fmaxf(m, __shfl_xor_sync(0xffffffffu, m, o));
        float e  = __expf(v - m);
        float eu = e * v;
        #pragma unroll
        for (int o = 8; o; o >>= 1) {
            e  += __shfl_xor_sync(0xffffffffu, e, o);
            eu += __shfl_xor_sync(0xffffffffu, eu, o);
        }
        if (j == 0) csum += __fdividef(eu, e);
    }

    // ---- block reduction of csum + lse_part ----
    float my = csum + lse_part;   // nonzero only on g16==0 lanes; harmless otherwise zero
    const int warp = t >> 5, lane = t & 31;
    #pragma unroll
    for (int o = 16; o; o >>= 1) my += __shfl_xor_sync(0xffffffffu, my, o);
    if (lane == 0) red[warp] = my;
    __syncthreads();
    if (t == 0) {
        float s = 0.f;
        #pragma unroll
        for (int w = 0; w < 8; w++) s += red[w];
        g_row_sum[n] = s;
        __threadfence();
        unsigned prev = atomicAdd(&g_ctr, 1u);
        is_last_sh = (prev == NROWS - 1);
    }
    __syncthreads();

    // ---- last block: deterministic final reduction ----
    if (is_last_sh) {
        float s = 0.f;
        #pragma unroll 4
        for (int i = t; i < NROWS; i += 256) s += g_row_sum[i];
        #pragma unroll
        for (int o = 16; o; o >>= 1) s += __shfl_xor_sync(0xffffffffu, s, o);
        if (lane == 0) red[warp] = s;
        __syncthreads();
        if (t == 0) {
            float v = 0.f;
            #pragma unroll
            for (int w = 0; w < 8; w++) v += red[w];
            out[0] = v * (1.0f / (float)NROWS);
            g_ctr = 0;   // reset for next graph replay
        }
    }
}

extern "C" void kernel_launch(void* const* d_in, const int* in_sizes, int n_in,
                              void* d_out, int out_size) {
    const float* x = nullptr;
    const float* pred = nullptr;
    for (int i = 0; i < n_in; i++) {
        if (in_sizes[i] == 32 * 4096 * 128)      x    = (const float*)d_in[i];
        else if (in_sizes[i] == 32 * 1024 * 128) pred = (const float*)d_in[i];
    }
    kl_fused_kernel<<<NROWS, 256>>>(x, pred, (float*)d_out);
}

// round 4
// speedup vs baseline: 1.2788x; 1.0412x over previous
#include <cuda_runtime.h>
#include <cuda_bf16.h>

// Shapes: batch_x [32,4096,128] -> N=4096 rows x 4096 (I=64 patches, L=64)
//         pred    [32,1024,128] -> N=4096 rows x 1024 (J=16 patches, L=64)
//
// Math (using sum_l q_jl = 1, so lse_i cancels inside the softmax over j):
//   dot_ij = q_j . x_i          (raw x)
//   u_ij   = ne_j - dot_ij      (ne_j = sum q log q)
//   loss   = mean_n [ sum_i ( sum_j softmax_j(u_ij) * u_ij + lse_i ) ]
#define NROWS 4096
#define SEQ   4096
#define PREDL 1024
#define XS_STRIDE 68
#define QS_STRIDE 68

__device__ float g_row_sum[NROWS];
__device__ unsigned g_ctr;   // zero-init; last block resets to 0 for graph replay

__device__ __forceinline__ unsigned long long pk2(float a, float b) {
    unsigned long long r;
    asm("mov.b64 %0, {%1, %2};" : "=l"(r) : "f"(a), "f"(b));
    return r;
}
__device__ __forceinline__ void fma2(unsigned long long& d,
                                     unsigned long long a, unsigned long long b) {
    asm("fma.rn.f32x2 %0, %1, %2, %0;" : "+l"(d) : "l"(a), "l"(b));
}
__device__ __forceinline__ float2 unpk2(unsigned long long v) {
    float2 r;
    asm("mov.b64 {%0, %1}, %2;" : "=f"(r.x), "=f"(r.y) : "l"(v));
    return r;
}

__global__ __launch_bounds__(256, 4)
void kl_fused_kernel(const float* __restrict__ x, const float* __restrict__ pred,
                     float* __restrict__ out) {
    __shared__ float xs[64 * XS_STRIDE];   // raw x patches [64][68]
    __shared__ float qs[16 * QS_STRIDE];   // softmax(pred) [16][68]
    __shared__ float ne[16];
    __shared__ float red[8];
    __shared__ int   is_last_sh;

    const int n    = blockIdx.x;
    const int t    = threadIdx.x;
    const int g16  = t & 15;
    const int p0   = t >> 4;
    const int warp = t >> 5;
    const int lane = t & 31;

    // ---- Phase A: raw x -> smem; lse_i per patch computed from load registers ----
    float lse_part = 0.f;
    {
        const float4* x4 = (const float4*)(x + (size_t)n * SEQ);
        float4 xv[4];
        #pragma unroll
        for (int k = 0; k < 4; k++) xv[k] = x4[t + 256 * k];
        #pragma unroll
        for (int k = 0; k < 4; k++)
            ((float4*)(xs + (p0 + 16 * k) * XS_STRIDE))[g16] = xv[k];
        #pragma unroll
        for (int k = 0; k < 4; k++) {
            float4 v = xv[k];
            float m = fmaxf(fmaxf(v.x, v.y), fmaxf(v.z, v.w));
            #pragma unroll
            for (int o = 8; o; o >>= 1) m = fmaxf(m, __shfl_xor_sync(0xffffffffu, m, o));
            float E = __expf(v.x - m) + __expf(v.y - m) + __expf(v.z - m) + __expf(v.w - m);
            #pragma unroll
            for (int o = 8; o; o >>= 1) E += __shfl_xor_sync(0xffffffffu, E, o);
            if (g16 == 0) lse_part += m + __logf(E);
        }
    }

    // ---- Phase B: pred patches -> q (smem) and ne_j ----
    {
        const float4* pr4 = (const float4*)(pred + (size_t)n * PREDL);
        float4 v = pr4[t];
        float m = fmaxf(fmaxf(v.x, v.y), fmaxf(v.z, v.w));
        #pragma unroll
        for (int o = 8; o; o >>= 1) m = fmaxf(m, __shfl_xor_sync(0xffffffffu, m, o));
        float e0 = __expf(v.x - m), e1 = __expf(v.y - m);
        float e2 = __expf(v.z - m), e3 = __expf(v.w - m);
        float E = e0 + e1 + e2 + e3;
        float S = e0 * v.x + e1 * v.y + e2 * v.z + e3 * v.w;
        #pragma unroll
        for (int o = 8; o; o >>= 1) {
            E += __shfl_xor_sync(0xffffffffu, E, o);
            S += __shfl_xor_sync(0xffffffffu, S, o);
        }
        float rinv = __frcp_rn(E);
        float lse  = m + __logf(E);
        ((float4*)(qs + p0 * QS_STRIDE))[g16] =
            make_float4(e0 * rinv, e1 * rinv, e2 * rinv, e3 * rinv);
        if (g16 == 0) ne[p0] = S * rinv - lse;
    }
    __syncthreads();

    // ---- Phase C: dot_ij with warp-broadcast x reads ----
    // warp w owns i-rows w*8..w*8+7; lane = (h = lane>>4, j = lane&15);
    // halves split l into interleaved float4 chunks c = 2*l4 + h.
    const int h = lane >> 4;
    const int j = lane & 15;
    unsigned long long acc[8];
    #pragma unroll
    for (int r = 0; r < 8; r++) acc[r] = 0ull;
    {
        const float4* q4 = (const float4*)(qs + j * QS_STRIDE);
        const float* xbase = xs + (warp * 8) * XS_STRIDE;
        #pragma unroll
        for (int l4 = 0; l4 < 8; l4++) {
            const int c = 2 * l4 + h;
            float4 qv = q4[c];
            unsigned long long qa = pk2(qv.x, qv.y);
            unsigned long long qb = pk2(qv.z, qv.w);
            #pragma unroll
            for (int r = 0; r < 8; r++) {
                float4 xv = ((const float4*)(xbase + r * XS_STRIDE))[c];
                fma2(acc[r], qa, pk2(xv.x, xv.y));
                fma2(acc[r], qb, pk2(xv.z, xv.w));
            }
        }
    }
    const float nej = ne[j];
    float u[8];
    #pragma unroll
    for (int r = 0; r < 8; r++) {
        float2 a = unpk2(acc[r]);
        float d = a.x + a.y;
        d += __shfl_xor_sync(0xffffffffu, d, 16);   // combine l-halves
        u[r] = nej - d;
    }

    // ---- softmax over j (16 lanes of this half); half h handles rows h*4..h*4+3 ----
    float csum = 0.f;
    #pragma unroll
    for (int k = 0; k < 4; k++) {
        float v = h ? u[k + 4] : u[k];
        float m = v;
        #pragma unroll
        for (int o = 8; o; o >>= 1) m = fmaxf(m, __shfl_xor_sync(0xffffffffu, m, o));
        float e  = __expf(v - m);
        float eu = e * v;
        #pragma unroll
        for (int o = 8; o; o >>= 1) {
            e  += __shfl_xor_sync(0xffffffffu, e, o);
            eu += __shfl_xor_sync(0xffffffffu, eu, o);
        }
        if (j == 0) csum += __fdividef(eu, e);
    }

    // ---- block reduction of csum + lse_part ----
    float my = csum + lse_part;
    #pragma unroll
    for (int o = 16; o; o >>= 1) my += __shfl_xor_sync(0xffffffffu, my, o);
    if (lane == 0) red[warp] = my;
    __syncthreads();
    if (t == 0) {
        float s = 0.f;
        #pragma unroll
        for (int w = 0; w < 8; w++) s += red[w];
        g_row_sum[n] = s;
        __threadfence();
        unsigned prev = atomicAdd(&g_ctr, 1u);
        is_last_sh = (prev == NROWS - 1);
    }
    __syncthreads();

    // ---- last block: deterministic final reduction ----
    if (is_last_sh) {
        float s = 0.f;
        #pragma unroll 4
        for (int i = t; i < NROWS; i += 256) s += g_row_sum[i];
        #pragma unroll
        for (int o = 16; o; o >>= 1) s += __shfl_xor_sync(0xffffffffu, s, o);
        if (lane == 0) red[warp] = s;
        __syncthreads();
        if (t == 0) {
            float v = 0.f;
            #pragma unroll
            for (int w = 0; w < 8; w++) v += red[w];
            out[0] = v * (1.0f / (float)NROWS);
            g_ctr = 0;
        }
    }
}

extern "C" void kernel_launch(void* const* d_in, const int* in_sizes, int n_in,
                              void* d_out, int out_size) {
    const float* x = nullptr;
    const float* pred = nullptr;
    for (int i = 0; i < n_in; i++) {
        if (in_sizes[i] == 32 * 4096 * 128)      x    = (const float*)d_in[i];
        else if (in_sizes[i] == 32 * 1024 * 128) pred = (const float*)d_in[i];
    }
    kl_fused_kernel<<<NROWS, 256>>>(x, pred, (float*)d_out);
}

// round 5
// speedup vs baseline: 1.6177x; 1.2650x over previous
#include <cuda_runtime.h>
#include <cuda_bf16.h>

// Shapes: batch_x [32,4096,128] -> N=4096 rows x 4096 (I=64 patches, L=64)
//         pred    [32,1024,128] -> N=4096 rows x 1024 (J=16 patches, L=64)
//
// Math (sum_l q_jl = 1 => lse_i cancels in softmax over j):
//   dot_ij = q_j . x_i (raw x);  u_ij = ne_j - dot_ij  (ne_j = sum q log q)
//   loss = mean_n [ sum_i ( sum_j softmax_j(u_ij)*u_ij + lse_i ) ]
//
// CTA = 128 threads processes ROWS_PER_CTA=2 n-rows. Transposed smem:
//   xt[l][i] (stride 68 words), qt[l][j] (stride 20 words), XOR-swizzled at
//   float4 granularity: chunk' = chunk ^ ((l>>2) & mask). Phase C: each thread
//   computes a 4i x 4j tile: per l-step 2 LDS.128 + 16 MACs (8 FFMA2).
#define NROWS 4096
#define SEQ   4096
#define PREDL 1024
#define ROWS_PER_CTA 2
#define NCTAS (NROWS / ROWS_PER_CTA)
#define XROW (64 * 68)   // words per n-row of xt
#define QROW (64 * 20)   // words per n-row of qt

__device__ float g_blk_sum[NCTAS];
__device__ unsigned g_ctr = 0;

__device__ __forceinline__ unsigned long long pk2(float a, float b) {
    unsigned long long r;
    asm("mov.b64 %0, {%1, %2};" : "=l"(r) : "f"(a), "f"(b));
    return r;
}
__device__ __forceinline__ void fma2(unsigned long long& d,
                                     unsigned long long a, unsigned long long b) {
    asm("fma.rn.f32x2 %0, %1, %2, %0;" : "+l"(d) : "l"(a), "l"(b));
}
__device__ __forceinline__ float2 unpk2(unsigned long long v) {
    float2 r;
    asm("mov.b64 {%0, %1}, %2;" : "=f"(r.x), "=f"(r.y) : "l"(v));
    return r;
}

__global__ __launch_bounds__(128, 5)
void kl_fused_kernel(const float* __restrict__ x, const float* __restrict__ pred,
                     float* __restrict__ out) {
    __shared__ float xt[ROWS_PER_CTA * XROW];   // 34.8KB
    __shared__ float qt[ROWS_PER_CTA * QROW];   // 10.2KB
    __shared__ __align__(16) float ne[ROWS_PER_CTA * 16];
    __shared__ float red[4];
    __shared__ int   is_last_sh;

    const int t    = threadIdx.x;
    const int g16  = t & 15;
    const int lane = t & 31;
    const int warp = t >> 5;
    const int n0   = blockIdx.x * ROWS_PER_CTA;

    float lse_part = 0.f;

    // ---- Phase A: x -> xt (transposed+swizzled); lse per patch from registers ----
    #pragma unroll
    for (int rr = 0; rr < ROWS_PER_CTA; rr++) {
        const float4* x4 = (const float4*)(x + (size_t)(n0 + rr) * SEQ);
        float* xbase = xt + rr * XROW;
        #pragma unroll
        for (int k = 0; k < 8; k++) {
            float4 v = x4[t + 128 * k];
            const int patch = (t >> 4) + 8 * k;     // i index
            const int c  = g16;                     // l-chunk (l>>2)
            const int l0 = 4 * c;
            const int pos = 4 * ((patch >> 2) ^ (c & 7)) + (patch & 3);
            xbase[(l0 + 0) * 68 + pos] = v.x;
            xbase[(l0 + 1) * 68 + pos] = v.y;
            xbase[(l0 + 2) * 68 + pos] = v.z;
            xbase[(l0 + 3) * 68 + pos] = v.w;
            // lse over the 16-thread group sharing this patch
            float m = fmaxf(fmaxf(v.x, v.y), fmaxf(v.z, v.w));
            #pragma unroll
            for (int o = 8; o; o >>= 1) m = fmaxf(m, __shfl_xor_sync(0xffffffffu, m, o));
            float E = __expf(v.x - m) + __expf(v.y - m) + __expf(v.z - m) + __expf(v.w - m);
            #pragma unroll
            for (int o = 8; o; o >>= 1) E += __shfl_xor_sync(0xffffffffu, E, o);
            if (g16 == 0) lse_part += m + __logf(E);
        }
    }

    // ---- Phase B: pred -> qt (transposed+swizzled) and ne_j ----
    #pragma unroll
    for (int rr = 0; rr < ROWS_PER_CTA; rr++) {
        const float4* pr4 = (const float4*)(pred + (size_t)(n0 + rr) * PREDL);
        float* qbase = qt + rr * QROW;
        #pragma unroll
        for (int k = 0; k < 2; k++) {
            float4 v = pr4[t + 128 * k];
            const int p0 = (t >> 4) + 8 * k;        // j index
            const int c  = g16;                     // l-chunk
            float m = fmaxf(fmaxf(v.x, v.y), fmaxf(v.z, v.w));
            #pragma unroll
            for (int o = 8; o; o >>= 1) m = fmaxf(m, __shfl_xor_sync(0xffffffffu, m, o));
            float e0 = __expf(v.x - m), e1 = __expf(v.y - m);
            float e2 = __expf(v.z - m), e3 = __expf(v.w - m);
            float E = e0 + e1 + e2 + e3;
            float S = e0 * v.x + e1 * v.y + e2 * v.z + e3 * v.w;
            #pragma unroll
            for (int o = 8; o; o >>= 1) {
                E += __shfl_xor_sync(0xffffffffu, E, o);
                S += __shfl_xor_sync(0xffffffffu, S, o);
            }
            float rinv = __frcp_rn(E);
            float lse  = m + __logf(E);
            const int l0 = 4 * c;
            const int pos = 4 * ((p0 >> 2) ^ (c & 3)) + (p0 & 3);
            qbase[(l0 + 0) * 20 + pos] = e0 * rinv;
            qbase[(l0 + 1) * 20 + pos] = e1 * rinv;
            qbase[(l0 + 2) * 20 + pos] = e2 * rinv;
            qbase[(l0 + 3) * 20 + pos] = e3 * rinv;
            if (g16 == 0) ne[rr * 16 + p0] = S * rinv - lse;
        }
    }
    __syncthreads();

    // ---- Phase C: 4i x 4j register tile per thread ----
    // thread: rr = t>>6, s = t&63, ia = s>>2 (i = 4ia+ri), ja = s&3 (j = 4ja+rj)
    const int rr = t >> 6;
    const int s  = t & 63;
    const int ia = s >> 2;
    const int ja = s & 3;

    unsigned long long acc[4][2];
    #pragma unroll
    for (int ri = 0; ri < 4; ri++) { acc[ri][0] = 0ull; acc[ri][1] = 0ull; }

    {
        const float* xbase = xt + rr * XROW;
        const float* qbase = qt + rr * QROW;
        #pragma unroll
        for (int lb = 0; lb < 16; lb++) {
            const float* xp = xbase + (4 * lb) * 68 + 4 * (ia ^ (lb & 7));
            const float* qp = qbase + (4 * lb) * 20 + 4 * (ja ^ (lb & 3));
            #pragma unroll
            for (int d = 0; d < 4; d++) {
                float4 xv = *(const float4*)(xp + d * 68);
                float4 qv = *(const float4*)(qp + d * 20);
                unsigned long long q01 = pk2(qv.x, qv.y);
                unsigned long long q23 = pk2(qv.z, qv.w);
                unsigned long long x0 = pk2(xv.x, xv.x);
                unsigned long long x1 = pk2(xv.y, xv.y);
                unsigned long long x2 = pk2(xv.z, xv.z);
                unsigned long long x3 = pk2(xv.w, xv.w);
                fma2(acc[0][0], x0, q01); fma2(acc[0][1], x0, q23);
                fma2(acc[1][0], x1, q01); fma2(acc[1][1], x1, q23);
                fma2(acc[2][0], x2, q01); fma2(acc[2][1], x2, q23);
                fma2(acc[3][0], x3, q01); fma2(acc[3][1], x3, q23);
            }
        }
    }

    // u_ij = ne_j - dot_ij; softmax over 16 j = 4 rj (in-thread) x 4 ja (lanes, xor 1,2)
    const float4 nev = *(const float4*)(ne + rr * 16 + 4 * ja);
    float csum = 0.f;
    #pragma unroll
    for (int ri = 0; ri < 4; ri++) {
        float2 d01 = unpk2(acc[ri][0]);
        float2 d23 = unpk2(acc[ri][1]);
        float u0 = nev.x - d01.x;
        float u1 = nev.y - d01.y;
        float u2 = nev.z - d23.x;
        float u3 = nev.w - d23.y;
        float m = fmaxf(fmaxf(u0, u1), fmaxf(u2, u3));
        m = fmaxf(m, __shfl_xor_sync(0xffffffffu, m, 1));
        m = fmaxf(m, __shfl_xor_sync(0xffffffffu, m, 2));
        float e0 = __expf(u0 - m), e1 = __expf(u1 - m);
        float e2 = __expf(u2 - m), e3 = __expf(u3 - m);
        float e  = e0 + e1 + e2 + e3;
        float eu = e0 * u0 + e1 * u1 + e2 * u2 + e3 * u3;
        e  += __shfl_xor_sync(0xffffffffu, e, 1);
        eu += __shfl_xor_sync(0xffffffffu, eu, 1);
        e  += __shfl_xor_sync(0xffffffffu, e, 2);
        eu += __shfl_xor_sync(0xffffffffu, eu, 2);
        if (ja == 0) csum += __fdividef(eu, e);
    }

    // ---- block reduction ----
    float my = csum + lse_part;
    #pragma unroll
    for (int o = 16; o; o >>= 1) my += __shfl_xor_sync(0xffffffffu, my, o);
    if (lane == 0) red[warp] = my;
    __syncthreads();
    if (t == 0) {
        float sum = red[0] + red[1] + red[2] + red[3];
        g_blk_sum[blockIdx.x] = sum;
        __threadfence();
        unsigned prev = atomicAdd(&g_ctr, 1u);
        is_last_sh = (prev == NCTAS - 1);
    }
    __syncthreads();

    // ---- last block: deterministic final reduction ----
    if (is_last_sh) {
        float sacc = 0.f;
        #pragma unroll 4
        for (int i = t; i < NCTAS; i += 128) sacc += g_blk_sum[i];
        #pragma unroll
        for (int o = 16; o; o >>= 1) sacc += __shfl_xor_sync(0xffffffffu, sacc, o);
        if (lane == 0) red[warp] = sacc;
        __syncthreads();
        if (t == 0) {
            out[0] = (red[0] + red[1] + red[2] + red[3]) * (1.0f / (float)NROWS);
            g_ctr = 0;
        }
    }
}

extern "C" void kernel_launch(void* const* d_in, const int* in_sizes, int n_in,
                              void* d_out, int out_size) {
    const float* x = nullptr;
    const float* pred = nullptr;
    for (int i = 0; i < n_in; i++) {
        if (in_sizes[i] == 32 * 4096 * 128)      x    = (const float*)d_in[i];
        else if (in_sizes[i] == 32 * 1024 * 128) pred = (const float*)d_in[i];
    }
    kl_fused_kernel<<<NCTAS, 128>>>(x, pred, (float*)d_out);
}